// round 7
// baseline (speedup 1.0000x reference)
#include <cuda_runtime.h>
#include <cuda_bf16.h>

// NeRF deterministic inverse-CDF sampling — divergence-free formulation.
// One warp per ray. Lane l owns bins 4l..4l+3.
//  1. lane-minor weight load + 1 warp scan -> exact sample-range boundaries jb
//     (identical fmaf on identical values across lanes -> exact partition of [0,128))
//  2. per-bin affine params (out_j = A*j + B) stored to smem (uniform stores)
//  3. bin index scattered at each nonempty bin's START position only (predicated
//     single store, no loop); interiors recovered by warp-wide inclusive MAX-scan
//     over the 128 owner slots (segment-id trick)
//  4. each lane gathers (A,B) for its own 4 consecutive samples, one STG.128.
// Zero divergent loops, zero per-sample branches.

#define RPB 8
#define FULL 0xffffffffu

__global__ __launch_bounds__(RPB * 32)
void nerf_sample_kernel(const float* __restrict__ rays_o,
                        const float* __restrict__ rays_d,
                        const float* __restrict__ weights,
                        float* __restrict__ out,
                        int R)
{
    __shared__ __align__(16) float2 s_ab[RPB][128];  // per-bin (A,B)
    __shared__ __align__(16) int    s_ow[RPB][128];  // owner-bin marks / scan input

    const int warp = threadIdx.x >> 5;
    const int lane = threadIdx.x & 31;
    const int ray  = blockIdx.x * RPB + warp;
    if (ray >= R) return;

    // ---- near/far cube intersection (bound=1); warp-redundant ----
    const float* o3 = rays_o + 3 * ray;
    const float* d3 = rays_d + 3 * ray;
    float nearv = -1e30f, farv = 1e30f;
#pragma unroll
    for (int a = 0; a < 3; ++a) {
        float oo  = __ldg(o3 + a);
        float dd  = __ldg(d3 + a) + 1e-15f;
        float inv = __fdividef(1.0f, dd);
        float t0  = (-1.0f - oo) * inv;
        float t1  = ( 1.0f - oo) * inv;
        nearv = fmaxf(nearv, fminf(t0, t1));
        farv  = fminf(farv,  fmaxf(t0, t1));
    }
    nearv = fmaxf(nearv, 0.05f);
    const float sstep = (farv - nearv) * (1.0f / 127.0f);

    // ---- lane-minor weight load: lane l owns w[4l..4l+3] ----
    const float* wrow = weights + (long long)ray * 127;
    const int base = 4 * lane;
    float w0 = __ldg(wrow + base)     + 1e-5f;
    float w1 = __ldg(wrow + base + 1) + 1e-5f;
    float w2 = __ldg(wrow + base + 2) + 1e-5f;
    float w3 = (lane < 31) ? (__ldg(wrow + base + 3) + 1e-5f) : 0.0f;

    // local inclusive prefix + one warp scan over lane totals
    const float s0 = w0;
    const float s1 = s0 + w1;
    const float s2 = s1 + w2;
    const float s3 = s2 + w3;

    float incl = s3;
#pragma unroll
    for (int d = 1; d < 32; d <<= 1) {
        float y = __shfl_up_sync(FULL, incl, d);
        if (lane >= d) incl += y;
    }
    float P = __shfl_up_sync(FULL, incl, 1);
    if (lane == 0) P = 0.0f;
    const float total = __shfl_sync(FULL, incl, 31);
    const float rtot  = __fdividef(1.0f, total);
    const float g     = rtot * 128.0f;   // identical in all lanes

    // unnormalized prefixes and normalized CDF boundaries for 4 bins
    const float m1 = P + s0, m2 = P + s1, m3 = P + s2;
    const float b0 = P    * rtot;
    const float b1 = m1   * rtot;
    const float b2 = m2   * rtot;
    const float b3 = m3   * rtot;
    const float b4 = incl * rtot;

    // sample-index boundaries; jb4(lane l) == jb0(lane l+1) exactly
    int jb0 = (int)ceilf(fmaf(P,    g, -0.5f));
    int jb4 = (int)ceilf(fmaf(incl, g, -0.5f));
    jb0 = min(max(jb0, 0), 128);
    jb4 = min(max(jb4, 0), 128);
    int jb1 = min(max((int)ceilf(fmaf(m1, g, -0.5f)), jb0), jb4);
    int jb2 = min(max((int)ceilf(fmaf(m2, g, -0.5f)), jb1), jb4);
    int jb3 = min(max((int)ceilf(fmaf(m3, g, -0.5f)), jb2), jb4);

    // per-bin affine params: out_j = A*j + B
    const float sA = sstep * 0.0078125f;   // sstep/128
    const float fi = (float)base;
    float2* abrow = s_ab[warp];
    int*    owrow = s_ow[warp];

#pragma unroll
    for (int k = 0; k < 4; ++k) {
        float blo = (k == 0) ? b0 : (k == 1) ? b1 : (k == 2) ? b2 : b3;
        float bhi = (k == 0) ? b1 : (k == 1) ? b2 : (k == 2) ? b3 : b4;
        float den  = bhi - blo;
        float rden = (den < 1e-5f) ? 1.0f : __fdividef(1.0f, den);
        float A = sA * rden;
        float B = fmaf(sstep, (fi + (float)k) + (0.00390625f - blo) * rden, nearv);
        abrow[base + k] = make_float2(A, B);
    }
    // init owner slots owned by this lane
    *reinterpret_cast<int4*>(owrow + base) = make_int4(0, 0, 0, 0);
    __syncwarp();

    // scatter bin index at each nonempty bin's start (disjoint addresses)
    if (jb0 < jb1) owrow[jb0] = base;
    if (jb1 < jb2) owrow[jb1] = base + 1;
    if (jb2 < jb3) owrow[jb2] = base + 2;
    if (jb3 < jb4) owrow[jb3] = base + 3;
    __syncwarp();

    // 128-wide inclusive max-scan (segment-id fill), lane-minor
    int4 ow = *reinterpret_cast<const int4*>(owrow + base);
    int q0 = ow.x;
    int q1 = max(q0, ow.y);
    int q2 = max(q1, ow.z);
    int q3 = max(q2, ow.w);

    int v = q3;
#pragma unroll
    for (int d = 1; d < 32; d <<= 1) {
        int y = __shfl_up_sync(FULL, v, d);
        if (lane >= d) v = max(v, y);
    }
    int ex = __shfl_up_sync(FULL, v, 1);
    if (lane == 0) ex = 0;
    const int i0 = max(ex, q0);
    const int i1 = max(ex, q1);
    const int i2 = max(ex, q2);
    const int i3 = max(ex, q3);

    // gather params, compute 4 consecutive samples, one STG.128
    float2 ab0 = abrow[i0];
    float2 ab1 = abrow[i1];
    float2 ab2 = abrow[i2];
    float2 ab3 = abrow[i3];
    float4 r;
    r.x = fmaf(ab0.x, (float)(base + 0), ab0.y);
    r.y = fmaf(ab1.x, (float)(base + 1), ab1.y);
    r.z = fmaf(ab2.x, (float)(base + 2), ab2.y);
    r.w = fmaf(ab3.x, (float)(base + 3), ab3.y);
    *reinterpret_cast<float4*>(out + (long long)ray * 128 + base) = r;
}

extern "C" void kernel_launch(void* const* d_in, const int* in_sizes, int n_in,
                              void* d_out, int out_size) {
    const float* rays_o  = (const float*)d_in[0];
    const float* rays_d  = (const float*)d_in[1];
    const float* weights = (const float*)d_in[2];
    float* out = (float*)d_out;

    const int R = in_sizes[0] / 3;   // 262144
    dim3 block(RPB * 32);
    dim3 grid((R + RPB - 1) / RPB);
    nerf_sample_kernel<<<grid, block>>>(rays_o, rays_d, weights, out, R);
}

// round 8
// speedup vs baseline: 1.2706x; 1.2706x over previous
#include <cuda_runtime.h>
#include <cuda_bf16.h>

// NeRF deterministic inverse-CDF sampling — divergence-free, conflict-free.
// One warp per ray. Lane l owns bins 4l..4l+3 (lane-minor).
//  1. COALESCED weight load (dense) -> smem transpose (dense STS.32 x4 +
//     LDS.128, both conflict-free) -> lane-minor registers.
//  2. 3 serial adds + one 32-wide warp scan; exact sample-range boundaries jb
//     (identical fmaf on identical values across lanes -> exact partition).
//  3. per-bin affine params (out_j = A*j+B) stored as float2 in TRANSPOSED
//     layout slot(i)=(i&3)*32+(i>>2): stride-8 dense STS.64, conflict-free.
//  4. bin index scattered only at each nonempty bin's start; interiors filled
//     by a warp inclusive MAX-scan over 128 owner slots (segment-id trick).
//  5. each lane gathers (A,B) for its 4 consecutive samples, one STG.128.
// Zero divergent loops; all structured smem accesses conflict-free.

#define RPB 8
#define FULL 0xffffffffu

__global__ __launch_bounds__(RPB * 32)
void nerf_sample_kernel(const float* __restrict__ rays_o,
                        const float* __restrict__ rays_d,
                        const float* __restrict__ weights,
                        float* __restrict__ out,
                        int R)
{
    __shared__ __align__(16) float2 s_ab[RPB][128];   // (A,B), transposed slots
    __shared__ __align__(16) int    s_tmp[RPB][128];  // transpose buf / owner marks

    const int warp = threadIdx.x >> 5;
    const int lane = threadIdx.x & 31;
    const int ray  = blockIdx.x * RPB + warp;
    if (ray >= R) return;

    float* swrow = reinterpret_cast<float*>(s_tmp[warp]);
    int*   owrow = s_tmp[warp];
    float2* abrow = s_ab[warp];

    // ---- near/far cube intersection (bound=1); warp-redundant ----
    const float* o3 = rays_o + 3 * ray;
    const float* d3 = rays_d + 3 * ray;
    float nearv = -1e30f, farv = 1e30f;
#pragma unroll
    for (int a = 0; a < 3; ++a) {
        float oo  = __ldg(o3 + a);
        float dd  = __ldg(d3 + a) + 1e-15f;
        float inv = __fdividef(1.0f, dd);
        float t0  = (-1.0f - oo) * inv;
        float t1  = ( 1.0f - oo) * inv;
        nearv = fmaxf(nearv, fminf(t0, t1));
        farv  = fminf(farv,  fmaxf(t0, t1));
    }
    nearv = fmaxf(nearv, 0.05f);
    const float sstep = (farv - nearv) * (1.0f / 127.0f);

    // ---- coalesced weight load (+eps), transpose to lane-minor via smem ----
    const float* wrow = weights + (long long)ray * 127;
    float a0 = __ldg(wrow + lane)      + 1e-5f;
    float a1 = __ldg(wrow + lane + 32) + 1e-5f;
    float a2 = __ldg(wrow + lane + 64) + 1e-5f;
    float a3 = (lane < 31) ? (__ldg(wrow + lane + 96) + 1e-5f) : 0.0f;  // pad w[127]=0

    swrow[lane]      = a0;   // dense STS.32, conflict-free
    swrow[lane + 32] = a1;
    swrow[lane + 64] = a2;
    swrow[lane + 96] = a3;
    __syncwarp();

    const int base = 4 * lane;
    float4 wv = *reinterpret_cast<const float4*>(swrow + base);  // LDS.128 dense
    __syncwarp();   // s_tmp reused as owner buffer below

    // ---- local prefix + one warp scan over lane totals ----
    const float s0 = wv.x;
    const float s1 = s0 + wv.y;
    const float s2 = s1 + wv.z;
    const float s3 = s2 + wv.w;

    float incl = s3;
#pragma unroll
    for (int d = 1; d < 32; d <<= 1) {
        float y = __shfl_up_sync(FULL, incl, d);
        if (lane >= d) incl += y;
    }
    float P = __shfl_up_sync(FULL, incl, 1);
    if (lane == 0) P = 0.0f;
    const float total = __shfl_sync(FULL, incl, 31);
    const float rtot  = __fdividef(1.0f, total);
    const float g     = rtot * 128.0f;   // identical in all lanes

    // normalized CDF boundaries of this lane's 4 bins
    const float m1 = P + s0, m2 = P + s1, m3 = P + s2;
    const float b0 = P    * rtot;
    const float b1 = m1   * rtot;
    const float b2 = m2   * rtot;
    const float b3 = m3   * rtot;
    const float b4 = incl * rtot;

    // sample-index boundaries; jb4(lane l) == jb0(lane l+1) exactly
    int jb0 = (int)ceilf(fmaf(P,    g, -0.5f));
    int jb4 = (int)ceilf(fmaf(incl, g, -0.5f));
    jb0 = min(max(jb0, 0), 128);
    jb4 = min(max(jb4, 0), 128);
    int jb1 = min(max((int)ceilf(fmaf(m1, g, -0.5f)), jb0), jb4);
    int jb2 = min(max((int)ceilf(fmaf(m2, g, -0.5f)), jb1), jb4);
    int jb3 = min(max((int)ceilf(fmaf(m3, g, -0.5f)), jb2), jb4);

    // ---- per-bin affine params, transposed slots: bin 4l+k -> slot k*32+l ----
    const float sA = sstep * 0.0078125f;   // sstep/128
    const float fi = (float)base;
#pragma unroll
    for (int k = 0; k < 4; ++k) {
        float blo = (k == 0) ? b0 : (k == 1) ? b1 : (k == 2) ? b2 : b3;
        float bhi = (k == 0) ? b1 : (k == 1) ? b2 : (k == 2) ? b3 : b4;
        float den  = bhi - blo;
        float rden = (den < 1e-5f) ? 1.0f : __fdividef(1.0f, den);
        float A = sA * rden;
        float B = fmaf(sstep, (fi + (float)k) + (0.00390625f - blo) * rden, nearv);
        abrow[k * 32 + lane] = make_float2(A, B);   // stride-8 dense, conflict-free
    }

    // ---- owner marks: init, scatter starts, max-scan fill ----
    *reinterpret_cast<int4*>(owrow + base) = make_int4(0, 0, 0, 0);
    __syncwarp();
    if (jb0 < jb1) owrow[jb0] = base;
    if (jb1 < jb2) owrow[jb1] = base + 1;
    if (jb2 < jb3) owrow[jb2] = base + 2;
    if (jb3 < jb4) owrow[jb3] = base + 3;
    __syncwarp();

    int4 ow = *reinterpret_cast<const int4*>(owrow + base);
    int q0 = ow.x;
    int q1 = max(q0, ow.y);
    int q2 = max(q1, ow.z);
    int q3 = max(q2, ow.w);

    int v = q3;
#pragma unroll
    for (int d = 1; d < 32; d <<= 1) {
        int y = __shfl_up_sync(FULL, v, d);
        if (lane >= d) v = max(v, y);
    }
    int ex = __shfl_up_sync(FULL, v, 1);
    if (lane == 0) ex = 0;
    const int i0 = max(ex, q0);
    const int i1 = max(ex, q1);
    const int i2 = max(ex, q2);
    const int i3 = max(ex, q3);

    // ---- gather (A,B) from transposed slots, 4 fma, one STG.128 ----
#define SLOT(i) ((((i) & 3) << 5) + ((i) >> 2))
    float2 ab0 = abrow[SLOT(i0)];
    float2 ab1 = abrow[SLOT(i1)];
    float2 ab2 = abrow[SLOT(i2)];
    float2 ab3 = abrow[SLOT(i3)];
#undef SLOT
    float4 r;
    r.x = fmaf(ab0.x, (float)(base + 0), ab0.y);
    r.y = fmaf(ab1.x, (float)(base + 1), ab1.y);
    r.z = fmaf(ab2.x, (float)(base + 2), ab2.y);
    r.w = fmaf(ab3.x, (float)(base + 3), ab3.y);
    *reinterpret_cast<float4*>(out + (long long)ray * 128 + base) = r;
}

extern "C" void kernel_launch(void* const* d_in, const int* in_sizes, int n_in,
                              void* d_out, int out_size) {
    const float* rays_o  = (const float*)d_in[0];
    const float* rays_d  = (const float*)d_in[1];
    const float* weights = (const float*)d_in[2];
    float* out = (float*)d_out;

    const int R = in_sizes[0] / 3;   // 262144
    dim3 block(RPB * 32);
    dim3 grid((R + RPB - 1) / RPB);
    nerf_sample_kernel<<<grid, block>>>(rays_o, rays_d, weights, out, R);
}

// round 9
// speedup vs baseline: 1.3968x; 1.0993x over previous
#include <cuda_runtime.h>
#include <cuda_bf16.h>

// NeRF deterministic inverse-CDF sampling — divergence-free, CDF-array form.
// One warp per ray. Lane l owns bins 4l..4l+3 (lane-minor).
//  1. coalesced weight load -> smem transpose -> lane-minor registers
//  2. 3 serial adds + one warp scan; exact sample boundaries jb via identical
//     fmaf on identical values across lanes (exact partition of [0,128));
//     boundary clamps reduced to a 3-deep chained min (fp cross-tree guard).
//  3. normalized CDF stored densely: one STS.128 per lane (+ lane31 cdf[128])
//  4. owner-bin ids: byte-packed marks — STS.32 init, STS.8 at bin starts,
//     LDS.32 readback, warp inclusive MAX-scan (segment-id fill)
//  5. per-sample: lo=cdf[i], hi=cdf[i+1], t=(u-lo)*rcp(hi-lo); one STG.128.

#define RPB 8
#define FULL 0xffffffffu

__global__ __launch_bounds__(RPB * 32)
void nerf_sample_kernel(const float* __restrict__ rays_o,
                        const float* __restrict__ rays_d,
                        const float* __restrict__ weights,
                        float* __restrict__ out,
                        int R)
{
    __shared__ __align__(16) float s_cdf[RPB][132];  // normalized CDF, 129 used
    __shared__ __align__(16) float s_w[RPB][128];    // transpose buffer
    __shared__ __align__(16) int   s_own[RPB][32];   // 128 owner bytes

    const int warp = threadIdx.x >> 5;
    const int lane = threadIdx.x & 31;
    const int ray  = blockIdx.x * RPB + warp;
    if (ray >= R) return;

    float* cdfrow = s_cdf[warp];
    float* wbuf   = s_w[warp];
    int*   ownrow = s_own[warp];

    // ---- near/far cube intersection (bound=1); warp-redundant ----
    const float* o3 = rays_o + 3 * ray;
    const float* d3 = rays_d + 3 * ray;
    float nearv = -1e30f, farv = 1e30f;
#pragma unroll
    for (int a = 0; a < 3; ++a) {
        float oo  = __ldg(o3 + a);
        float dd  = __ldg(d3 + a) + 1e-15f;
        float inv = __fdividef(1.0f, dd);
        float oi  = oo * inv;
        float t0  = -inv - oi;
        float t1  =  inv - oi;
        nearv = fmaxf(nearv, fminf(t0, t1));
        farv  = fminf(farv,  fmaxf(t0, t1));
    }
    nearv = fmaxf(nearv, 0.05f);
    const float sstep = (farv - nearv) * (1.0f / 127.0f);

    // ---- coalesced weight load (+eps), transpose to lane-minor ----
    const float* wrow = weights + (long long)ray * 127;
    float a0 = __ldg(wrow + lane)      + 1e-5f;
    float a1 = __ldg(wrow + lane + 32) + 1e-5f;
    float a2 = __ldg(wrow + lane + 64) + 1e-5f;
    float a3 = (lane < 31) ? (__ldg(wrow + lane + 96) + 1e-5f) : 0.0f;

    wbuf[lane]      = a0;
    wbuf[lane + 32] = a1;
    wbuf[lane + 64] = a2;
    wbuf[lane + 96] = a3;
    __syncwarp();

    const int base = 4 * lane;
    float4 wv = *reinterpret_cast<const float4*>(wbuf + base);

    // ---- local prefix + one warp scan over lane totals ----
    const float s0 = wv.x;
    const float s1 = s0 + wv.y;
    const float s2 = s1 + wv.z;
    const float s3 = s2 + wv.w;

    float incl = s3;
#pragma unroll
    for (int d = 1; d < 32; d <<= 1) {
        float y = __shfl_up_sync(FULL, incl, d);
        if (lane >= d) incl += y;
    }
    float P = __shfl_up_sync(FULL, incl, 1);
    if (lane == 0) P = 0.0f;
    const float total = __shfl_sync(FULL, incl, 31);
    const float rtot  = __fdividef(1.0f, total);
    const float g     = rtot * 128.0f;   // identical in all lanes

    // unnormalized boundaries
    const float m1 = P + s0, m2 = P + s1, m3 = P + s2;

    // sample-index boundaries; jb4(lane l) == jb0(lane l+1) exactly.
    // arg >= -0.5 -> ceil >= -0.0 -> no low clamp; arg <= 127.5+eps -> <=128.
    int jb0 = (int)ceilf(fmaf(P,    g, -0.5f));
    int jb1 = (int)ceilf(fmaf(m1,   g, -0.5f));
    int jb2 = (int)ceilf(fmaf(m2,   g, -0.5f));
    int jb3 = (int)ceilf(fmaf(m3,   g, -0.5f));
    int jb4 = (int)ceilf(fmaf(incl, g, -0.5f));
    // guard only the cross-tree fp hazard (m's vs scanned incl), chained:
    jb3 = min(jb3, jb4);
    jb2 = min(jb2, jb3);
    jb1 = min(jb1, jb2);

    // ---- store normalized CDF densely + init owner bytes ----
    float4 c4;
    c4.x = P  * rtot;
    c4.y = m1 * rtot;
    c4.z = m2 * rtot;
    c4.w = m3 * rtot;
    *reinterpret_cast<float4*>(cdfrow + base) = c4;
    if (lane == 31) cdfrow[128] = incl * rtot;   // cdf[128] ~= 1
    ownrow[lane] = 0;
    __syncwarp();

    // ---- scatter bin id (byte) at each nonempty bin's start ----
    char* ownb = reinterpret_cast<char*>(ownrow);
    if (jb0 < jb1) ownb[jb0] = (char)(base);
    if (jb1 < jb2) ownb[jb1] = (char)(base + 1);
    if (jb2 < jb3) ownb[jb2] = (char)(base + 2);
    if (jb3 < jb4) ownb[jb3] = (char)(base + 3);
    __syncwarp();

    // ---- owner recovery: byte extract + warp inclusive MAX-scan ----
    const int ow = ownrow[lane];
    int q0 = ow & 0xff;
    int q1 = max(q0, (ow >> 8)  & 0xff);
    int q2 = max(q1, (ow >> 16) & 0xff);
    int q3 = max(q2, (ow >> 24) & 0xff);

    int v = q3;
#pragma unroll
    for (int d = 1; d < 32; d <<= 1) {
        int y = __shfl_up_sync(FULL, v, d);
        if (lane >= d) v = max(v, y);
    }
    int ex = __shfl_up_sync(FULL, v, 1);
    if (lane == 0) ex = 0;
    const int i0 = max(ex, q0);
    const int i1 = max(ex, q1);
    const int i2 = max(ex, q2);
    const int i3 = max(ex, q3);

    // ---- per-sample interpolation from CDF array, one STG.128 ----
    const float u0 = fmaf((float)base, 0.0078125f, 0.00390625f);  // (4l+0.5)/128
    float lo0 = cdfrow[i0], hi0 = cdfrow[i0 + 1];
    float lo1 = cdfrow[i1], hi1 = cdfrow[i1 + 1];
    float lo2 = cdfrow[i2], hi2 = cdfrow[i2 + 1];
    float lo3 = cdfrow[i3], hi3 = cdfrow[i3 + 1];

    float d0 = hi0 - lo0, d1 = hi1 - lo1, d2 = hi2 - lo2, d3v = hi3 - lo3;
    float r0 = (d0 < 1e-5f) ? 1.0f : __fdividef(1.0f, d0);
    float r1 = (d1 < 1e-5f) ? 1.0f : __fdividef(1.0f, d1);
    float r2 = (d2 < 1e-5f) ? 1.0f : __fdividef(1.0f, d2);
    float r3 = (d3v < 1e-5f) ? 1.0f : __fdividef(1.0f, d3v);

    float4 rr;
    rr.x = fmaf(sstep, (float)i0 + (u0                - lo0) * r0, nearv);
    rr.y = fmaf(sstep, (float)i1 + (u0 + 0.0078125f   - lo1) * r1, nearv);
    rr.z = fmaf(sstep, (float)i2 + (u0 + 0.015625f    - lo2) * r2, nearv);
    rr.w = fmaf(sstep, (float)i3 + (u0 + 0.0234375f   - lo3) * r3, nearv);
    *reinterpret_cast<float4*>(out + (long long)ray * 128 + base) = rr;
}

extern "C" void kernel_launch(void* const* d_in, const int* in_sizes, int n_in,
                              void* d_out, int out_size) {
    const float* rays_o  = (const float*)d_in[0];
    const float* rays_d  = (const float*)d_in[1];
    const float* weights = (const float*)d_in[2];
    float* out = (float*)d_out;

    const int R = in_sizes[0] / 3;   // 262144
    dim3 block(RPB * 32);
    dim3 grid((R + RPB - 1) / RPB);
    nerf_sample_kernel<<<grid, block>>>(rays_o, rays_d, weights, out, R);
}